// round 2
// baseline (speedup 1.0000x reference)
#include <cuda_runtime.h>
#include <cstdint>

// ---------------------------------------------------------------------------
// out[b,o,v,l] = sum_c W[o,c] * (M x)[b,c,v,l] + bias[o]
// M = a*I + a(1-a)A + a(1-a)^2 A^2 + (1-a)^3 A^3,  a = 0.05
// A = row-normalized (adj + I).
// x (256,32,207,12) f32, adj (207,207), W (32,32), b (32).
// ---------------------------------------------------------------------------

#define NN    207
#define BATCH 256
#define CH    32
#define LT    12
#define ROW4  621            // 207*12/4 float4 per (b,c) slab

static __device__ float  g_a [NN * NN];
static __device__ float  g_a2[NN * NN];
static __device__ float  g_Mt[NN * NN];            // Mt[w*207+v] = M[v][w]
static __device__ float4 g_u [BATCH * CH * ROW4];  // channel-mixed intermediate

typedef unsigned long long ull;

#define FMA_F32X2(d, a, b, c) \
    asm("fma.rn.f32x2 %0, %1, %2, %3;" : "=l"(d) : "l"(a), "l"(b), "l"(c))

__device__ __forceinline__ ull pack2(float x) {
    ull r;
    unsigned int xi = __float_as_uint(x);
    asm("mov.b64 %0, {%1, %1};" : "=l"(r) : "r"(xi));
    return r;
}

// ---------------------------------------------------------------------------
// K1: row-normalize (adj + I)
// ---------------------------------------------------------------------------
__global__ void k_norm_adj(const float* __restrict__ adj) {
    int v = blockIdx.x;
    int t = threadIdx.x;
    __shared__ float red[256];
    float s = 0.f;
    for (int w = t; w < NN; w += 256) s += adj[v * NN + w];
    red[t] = s;
    __syncthreads();
    for (int k = 128; k > 0; k >>= 1) {
        if (t < k) red[t] += red[t + k];
        __syncthreads();
    }
    float inv = 1.f / (red[0] + 1.f);
    for (int w = t; w < NN; w += 256) {
        float e = adj[v * NN + w] + (w == v ? 1.f : 0.f);
        g_a[v * NN + w] = e * inv;
    }
}

// ---------------------------------------------------------------------------
// K2: a2 = a @ a
// ---------------------------------------------------------------------------
__global__ void k_a2() {
    int v = blockIdx.x;
    int t = threadIdx.x;
    __shared__ float av[NN];
    for (int w = t; w < NN; w += 224) av[w] = g_a[v * NN + w];
    __syncthreads();
    if (t < NN) {
        float acc = 0.f;
        #pragma unroll 4
        for (int w = 0; w < NN; ++w) acc = fmaf(av[w], g_a[w * NN + t], acc);
        g_a2[v * NN + t] = acc;
    }
}

// ---------------------------------------------------------------------------
// K3: a3 = a2 @ a -> combine into Mt (transposed)
// ---------------------------------------------------------------------------
__global__ void k_m() {
    int v = blockIdx.x;
    int t = threadIdx.x;
    __shared__ float av[NN], a2v[NN];
    for (int w = t; w < NN; w += 224) {
        av[w]  = g_a [v * NN + w];
        a2v[w] = g_a2[v * NN + w];
    }
    __syncthreads();
    if (t < NN) {
        float a3 = 0.f;
        #pragma unroll 4
        for (int w = 0; w < NN; ++w) a3 = fmaf(a2v[w], g_a[w * NN + t], a3);
        float m = 0.0475f * av[t] + 0.045125f * a2v[t] + 0.857375f * a3;
        if (t == v) m += 0.05f;
        g_Mt[t * NN + v] = m;
    }
}

// ---------------------------------------------------------------------------
// K4: channel mix  u[b,o,w,l] = sum_c W[o,c] x[b,c,w,l]
// block 128 = 8 o-groups x 16 nodes; each thread: 4 o x 12 l (24 f32x2 accs)
// ---------------------------------------------------------------------------
#define WT 16
__global__ void __launch_bounds__(128) k_chanmix(const float* __restrict__ x,
                                                 const float* __restrict__ W) {
    int b  = blockIdx.y;
    int w0 = blockIdx.x * WT;
    int nw = NN - w0; if (nw > WT) nw = WT;
    int t  = threadIdx.x;

    __shared__ __align__(16) float xs[CH * WT * LT];  // 24.6 KB, [c][wi][l]
    __shared__ ull Ws2[CH * CH];                      // 8 KB, splatted W

    for (int i = t; i < CH * CH; i += 128) Ws2[i] = pack2(W[i]);

    int nload = CH * nw * 3;                          // float4 count
    for (int i = t; i < nload; i += 128) {
        int c  = i / (nw * 3);
        int r  = i - c * nw * 3;
        int wi = r / 3;
        int l4 = r - wi * 3;
        const float* src = x + ((size_t)(b * CH + c) * NN + (w0 + wi)) * LT + l4 * 4;
        *(float4*)&xs[(c * WT + wi) * LT + l4 * 4] = *(const float4*)src;
    }
    __syncthreads();

    int og = t >> 4;       // 0..7  -> o = og*4 + j
    int wi = t & 15;
    if (wi < nw) {
        ull acc[4][6];
        #pragma unroll
        for (int j = 0; j < 4; ++j)
            #pragma unroll
            for (int k = 0; k < 6; ++k) acc[j][k] = 0ull;

        #pragma unroll 4
        for (int c = 0; c < CH; ++c) {
            const ull* xp = (const ull*)&xs[(c * WT + wi) * LT];
            ull u0 = xp[0], u1 = xp[1], u2 = xp[2], u3 = xp[3], u4 = xp[4], u5 = xp[5];
            #pragma unroll
            for (int j = 0; j < 4; ++j) {
                ull ww = Ws2[(og * 4 + j) * CH + c];
                FMA_F32X2(acc[j][0], ww, u0, acc[j][0]);
                FMA_F32X2(acc[j][1], ww, u1, acc[j][1]);
                FMA_F32X2(acc[j][2], ww, u2, acc[j][2]);
                FMA_F32X2(acc[j][3], ww, u3, acc[j][3]);
                FMA_F32X2(acc[j][4], ww, u4, acc[j][4]);
                FMA_F32X2(acc[j][5], ww, u5, acc[j][5]);
            }
        }

        #pragma unroll
        for (int j = 0; j < 4; ++j) {
            int o = og * 4 + j;
            float4* up = g_u + ((size_t)(b * CH + o) * NN + (w0 + wi)) * 3;
            ull* up8 = (ull*)up;
            up8[0] = acc[j][0]; up8[1] = acc[j][1]; up8[2] = acc[j][2];
            up8[3] = acc[j][3]; up8[4] = acc[j][4]; up8[5] = acc[j][5];
        }
    }
}

// ---------------------------------------------------------------------------
// K5: node mix  out[b,o,v,:] = sum_w M[v,w] u[b,o,w,:] + bias[o]
// block 224 = thread-per-v, covering 4 o's of one b (24 f32x2 accs/thread)
// ---------------------------------------------------------------------------
__global__ void __launch_bounds__(224) k_nodemix(const float* __restrict__ bias,
                                                float* __restrict__ out) {
    int og = blockIdx.x;     // 0..7 -> o = og*4 + g
    int b  = blockIdx.y;
    int t  = threadIdx.x;

    __shared__ __align__(16) float4 us4[4 * ROW4];   // 39.7 KB

    const float4* up = g_u + (size_t)(b * CH + og * 4) * ROW4;
    for (int i = t; i < 4 * ROW4; i += 224) us4[i] = up[i];
    __syncthreads();

    if (t < NN) {
        ull acc[4][6];
        #pragma unroll
        for (int g = 0; g < 4; ++g)
            #pragma unroll
            for (int k = 0; k < 6; ++k) acc[g][k] = 0ull;

        const float* mt = g_Mt + t;                  // coalesced across threads
        const ull*   us = (const ull*)us4;

        #pragma unroll 2
        for (int w = 0; w < NN; ++w) {
            ull mm = pack2(__ldg(mt + w * NN));
            #pragma unroll
            for (int g = 0; g < 4; ++g) {
                const ull* uw = us + g * (ROW4 * 2) + w * 6;
                ull p0 = uw[0], p1 = uw[1], p2 = uw[2];
                ull p3 = uw[3], p4 = uw[4], p5 = uw[5];
                FMA_F32X2(acc[g][0], mm, p0, acc[g][0]);
                FMA_F32X2(acc[g][1], mm, p1, acc[g][1]);
                FMA_F32X2(acc[g][2], mm, p2, acc[g][2]);
                FMA_F32X2(acc[g][3], mm, p3, acc[g][3]);
                FMA_F32X2(acc[g][4], mm, p4, acc[g][4]);
                FMA_F32X2(acc[g][5], mm, p5, acc[g][5]);
            }
        }

        #pragma unroll
        for (int g = 0; g < 4; ++g) {
            float bv = bias[og * 4 + g];
            float r[12];
            #pragma unroll
            for (int k = 0; k < 6; ++k) {
                r[2*k]   = __uint_as_float((unsigned)(acc[g][k]      )) + bv;
                r[2*k+1] = __uint_as_float((unsigned)(acc[g][k] >> 32)) + bv;
            }
            float* op = out + ((size_t)(b * CH + og * 4 + g) * NN + t) * LT;
            *(float4*)(op + 0) = *(float4*)(r + 0);
            *(float4*)(op + 4) = *(float4*)(r + 4);
            *(float4*)(op + 8) = *(float4*)(r + 8);
        }
    }
}

// ---------------------------------------------------------------------------
extern "C" void kernel_launch(void* const* d_in, const int* in_sizes, int n_in,
                              void* d_out, int out_size) {
    const float* x   = (const float*)d_in[0];
    const float* adj = (const float*)d_in[1];
    const float* W   = (const float*)d_in[2];
    const float* bia = (const float*)d_in[3];
    float* out = (float*)d_out;

    k_norm_adj<<<NN, 256>>>(adj);
    k_a2      <<<NN, 224>>>();
    k_m       <<<NN, 224>>>();
    k_chanmix <<<dim3((NN + WT - 1) / WT, BATCH), 128>>>(x, W);
    k_nodemix <<<dim3(CH / 4, BATCH), 224>>>(bia, out);
}

// round 4
// speedup vs baseline: 1.2907x; 1.2907x over previous
#include <cuda_runtime.h>
#include <cstdint>

// ---------------------------------------------------------------------------
// out[b,o,v,l] = sum_c W[o,c] * (M x)[b,c,v,l] + bias[o]
// M = 0.05*I + 0.0475*A + 0.045125*A^2 + 0.857375*A^3,  A = row-norm(adj+I)
// x (256,32,207,12) f32, adj (207,207), W (32,32), b (32).
// fp32 f32x2-FMA path (tcgen05 unavailable: harness builds via compute_103).
// ---------------------------------------------------------------------------

#define NN    207
#define NP    208            // padded v for 8B-aligned M loads
#define BATCH 256
#define CH    32
#define LT    12
#define ROW4  621            // 207*12/4 float4 per (b,c) slab

static __device__ float  g_a  [NN * NN];
static __device__ float  g_a2 [NN * NN];
static __device__ float  g_Mt2[NN * NP];           // Mt2[w*208+v] = M[v][w], col 207 = 0
static __device__ float4 g_u  [BATCH * CH * ROW4]; // channel-mixed intermediate

typedef unsigned long long ull;

#define FMA_F32X2(d, a, b, c) \
    asm("fma.rn.f32x2 %0, %1, %2, %3;" : "=l"(d) : "l"(a), "l"(b), "l"(c))

__device__ __forceinline__ ull pack2(float x) {
    ull r; unsigned xi = __float_as_uint(x);
    asm("mov.b64 %0, {%1, %1};" : "=l"(r) : "r"(xi));
    return r;
}

// ---------------------------------------------------------------------------
// K1: row-normalize (adj + I)
// ---------------------------------------------------------------------------
__global__ void k_norm_adj(const float* __restrict__ adj) {
    int v = blockIdx.x, t = threadIdx.x;
    __shared__ float red[256];
    float s = 0.f;
    for (int w = t; w < NN; w += 256) s += adj[v * NN + w];
    red[t] = s; __syncthreads();
    for (int k = 128; k > 0; k >>= 1) { if (t < k) red[t] += red[t + k]; __syncthreads(); }
    float inv = 1.f / (red[0] + 1.f);
    for (int w = t; w < NN; w += 256)
        g_a[v * NN + w] = (adj[v * NN + w] + (w == v ? 1.f : 0.f)) * inv;
}

// K2: a2 = a @ a
__global__ void k_a2() {
    int v = blockIdx.x, t = threadIdx.x;
    __shared__ float av[NN];
    for (int w = t; w < NN; w += 224) av[w] = g_a[v * NN + w];
    __syncthreads();
    if (t < NN) {
        float acc = 0.f;
        #pragma unroll 4
        for (int w = 0; w < NN; ++w) acc = fmaf(av[w], g_a[w * NN + t], acc);
        g_a2[v * NN + t] = acc;
    }
}

// K3: M = 0.05 I + 0.0475 a + 0.045125 a2 + 0.857375 a3 ; store transposed+padded
__global__ void k_m() {
    int v = blockIdx.x, t = threadIdx.x;
    __shared__ float av[NN], a2v[NN];
    for (int w = t; w < NN; w += 224) { av[w] = g_a[v*NN+w]; a2v[w] = g_a2[v*NN+w]; }
    __syncthreads();
    if (t < NN) {
        float a3 = 0.f;
        #pragma unroll 4
        for (int w = 0; w < NN; ++w) a3 = fmaf(a2v[w], g_a[w * NN + t], a3);
        float m = 0.0475f * av[t] + 0.045125f * a2v[t] + 0.857375f * a3;
        if (t == v) m += 0.05f;
        g_Mt2[t * NP + v] = m;          // Mt2[w][v] = M[v][w]
    }
    if (blockIdx.x == 0 && t < NN) g_Mt2[t * NP + NN] = 0.f;  // pad column
}

// ---------------------------------------------------------------------------
// K4: channel mix  u[b,o,w,l] = sum_c W[o,c] x[b,c,w,l]   (R2 version, 56us)
// block 128 = 8 o-groups x 16 nodes; each thread: 4 o x 12 l (24 f32x2 accs)
// ---------------------------------------------------------------------------
#define WT 16
__global__ void __launch_bounds__(128) k_chanmix(const float* __restrict__ x,
                                                 const float* __restrict__ W) {
    int b  = blockIdx.y;
    int w0 = blockIdx.x * WT;
    int nw = NN - w0; if (nw > WT) nw = WT;
    int t  = threadIdx.x;

    __shared__ __align__(16) float xs[CH * WT * LT];  // 24.6 KB, [c][wi][l]
    __shared__ ull Ws2[CH * CH];                      // 8 KB, splatted W

    for (int i = t; i < CH * CH; i += 128) Ws2[i] = pack2(W[i]);

    int nload = CH * nw * 3;
    for (int i = t; i < nload; i += 128) {
        int c  = i / (nw * 3);
        int r  = i - c * nw * 3;
        int wi = r / 3;
        int l4 = r - wi * 3;
        const float* src = x + ((size_t)(b * CH + c) * NN + (w0 + wi)) * LT + l4 * 4;
        *(float4*)&xs[(c * WT + wi) * LT + l4 * 4] = *(const float4*)src;
    }
    __syncthreads();

    int og = t >> 4;
    int wi = t & 15;
    if (wi < nw) {
        ull acc[4][6];
        #pragma unroll
        for (int j = 0; j < 4; ++j)
            #pragma unroll
            for (int k = 0; k < 6; ++k) acc[j][k] = 0ull;

        #pragma unroll 4
        for (int c = 0; c < CH; ++c) {
            const ull* xp = (const ull*)&xs[(c * WT + wi) * LT];
            ull u0 = xp[0], u1 = xp[1], u2 = xp[2], u3 = xp[3], u4 = xp[4], u5 = xp[5];
            #pragma unroll
            for (int j = 0; j < 4; ++j) {
                ull ww = Ws2[(og * 4 + j) * CH + c];
                FMA_F32X2(acc[j][0], ww, u0, acc[j][0]);
                FMA_F32X2(acc[j][1], ww, u1, acc[j][1]);
                FMA_F32X2(acc[j][2], ww, u2, acc[j][2]);
                FMA_F32X2(acc[j][3], ww, u3, acc[j][3]);
                FMA_F32X2(acc[j][4], ww, u4, acc[j][4]);
                FMA_F32X2(acc[j][5], ww, u5, acc[j][5]);
            }
        }

        #pragma unroll
        for (int j = 0; j < 4; ++j) {
            int o = og * 4 + j;
            ull* up8 = (ull*)(g_u + ((size_t)(b * CH + o) * NN + (w0 + wi)) * 3);
            up8[0] = acc[j][0]; up8[1] = acc[j][1]; up8[2] = acc[j][2];
            up8[3] = acc[j][3]; up8[4] = acc[j][4]; up8[5] = acc[j][5];
        }
    }
}

// ---------------------------------------------------------------------------
// K5: node mix  out[b,o,v,:] = sum_w M[v,w] u[b,o,w,:] + bias[o]
// block 128: one b x one o-PAIR; thread = 2 consecutive v (24 f32x2 accs)
// per w per thread: 1 LDG.64 (M) + 6 LDS.128 (u bcast) + 2 pack + 24 FMA2
// -> fma-pipe-bound; ~80 regs -> ~6 blocks/SM
// ---------------------------------------------------------------------------
__global__ void __launch_bounds__(128) k_nodemix(const float* __restrict__ bias,
                                                float* __restrict__ out) {
    int op = blockIdx.x;          // o = op*2 + g
    int b  = blockIdx.y;
    int t  = threadIdx.x;

    __shared__ __align__(16) float4 us4[2 * ROW4];   // 19.9 KB

    const float4* up = g_u + (size_t)(b * CH + op * 2) * ROW4;
    for (int i = t; i < 2 * ROW4; i += 128) us4[i] = up[i];
    __syncthreads();

    if (t < 104) {
        int v0 = t * 2;
        ull acc[2][2][6];         // [vi][g][lpair]
        #pragma unroll
        for (int vi = 0; vi < 2; ++vi)
            #pragma unroll
            for (int g = 0; g < 2; ++g)
                #pragma unroll
                for (int k = 0; k < 6; ++k) acc[vi][g][k] = 0ull;

        #pragma unroll 3
        for (int w = 0; w < NN; ++w) {
            float2 mv = __ldg((const float2*)(g_Mt2 + (size_t)w * NP + v0));
            ull m0 = pack2(mv.x);
            ull m1 = pack2(mv.y);
            #pragma unroll
            for (int g = 0; g < 2; ++g) {
                const float4* u4 = us4 + g * ROW4 + w * 3;
                float4 f0 = u4[0], f1 = u4[1], f2 = u4[2];
                ull p0 = *(ull*)&f0.x, p1 = *(ull*)&f0.z;
                ull p2 = *(ull*)&f1.x, p3 = *(ull*)&f1.z;
                ull p4 = *(ull*)&f2.x, p5 = *(ull*)&f2.z;
                FMA_F32X2(acc[0][g][0], m0, p0, acc[0][g][0]);
                FMA_F32X2(acc[0][g][1], m0, p1, acc[0][g][1]);
                FMA_F32X2(acc[0][g][2], m0, p2, acc[0][g][2]);
                FMA_F32X2(acc[0][g][3], m0, p3, acc[0][g][3]);
                FMA_F32X2(acc[0][g][4], m0, p4, acc[0][g][4]);
                FMA_F32X2(acc[0][g][5], m0, p5, acc[0][g][5]);
                FMA_F32X2(acc[1][g][0], m1, p0, acc[1][g][0]);
                FMA_F32X2(acc[1][g][1], m1, p1, acc[1][g][1]);
                FMA_F32X2(acc[1][g][2], m1, p2, acc[1][g][2]);
                FMA_F32X2(acc[1][g][3], m1, p3, acc[1][g][3]);
                FMA_F32X2(acc[1][g][4], m1, p4, acc[1][g][4]);
                FMA_F32X2(acc[1][g][5], m1, p5, acc[1][g][5]);
            }
        }

        #pragma unroll
        for (int vi = 0; vi < 2; ++vi) {
            int v = v0 + vi;
            if (v < NN) {
                #pragma unroll
                for (int g = 0; g < 2; ++g) {
                    float bv = __ldg(bias + op * 2 + g);
                    float r[12];
                    #pragma unroll
                    for (int k = 0; k < 6; ++k) {
                        r[2*k]   = __uint_as_float((unsigned)(acc[vi][g][k]      )) + bv;
                        r[2*k+1] = __uint_as_float((unsigned)(acc[vi][g][k] >> 32)) + bv;
                    }
                    float* op_ptr = out + ((size_t)(b * CH + op * 2 + g) * NN + v) * LT;
                    *(float4*)(op_ptr + 0) = *(float4*)(r + 0);
                    *(float4*)(op_ptr + 4) = *(float4*)(r + 4);
                    *(float4*)(op_ptr + 8) = *(float4*)(r + 8);
                }
            }
        }
    }
}

// ---------------------------------------------------------------------------
extern "C" void kernel_launch(void* const* d_in, const int* in_sizes, int n_in,
                              void* d_out, int out_size) {
    const float* x   = (const float*)d_in[0];
    const float* adj = (const float*)d_in[1];
    const float* W   = (const float*)d_in[2];
    const float* bia = (const float*)d_in[3];
    float* out = (float*)d_out;

    k_norm_adj<<<NN, 256>>>(adj);
    k_a2      <<<NN, 224>>>();
    k_m       <<<NN, 224>>>();
    k_chanmix <<<dim3((NN + WT - 1) / WT, BATCH), 128>>>(x, W);
    k_nodemix <<<dim3(CH / 2, BATCH), 128>>>(bia, out);
}

// round 5
// speedup vs baseline: 1.8958x; 1.4688x over previous
#include <cuda_runtime.h>
#include <cuda_bf16.h>
#include <cstdint>

// ---------------------------------------------------------------------------
// out[b,o,v,l] = sum_c W[o,c] * (M x)[b,c,v,l] + bias[o]
// M = 0.05*I + 0.0475*A + 0.045125*A^2 + 0.857375*A^3,  A = row-norm(adj+I)
// Path: fold diffusion into M; chanmix -> split-bf16 U[j][w] (j=(b,o,l));
// mma.sync bf16 3-pass GEMM D[v,j] = M[v,:]·U[j,:]  (tcgen05 unavailable:
// harness builds via compute_103 virtual arch; HMMA/ldmatrix are baseline).
// ---------------------------------------------------------------------------

#define NN    207
#define KP    208                 // padded K (w), 13 x k16
#define MP    256                 // padded M (v)
#define BATCH 256
#define CH    32
#define LT    12
#define NJ    (BATCH * CH * LT)   // 98304
#define JT    64                  // j per CTA

typedef unsigned long long ull;
typedef unsigned int uint;

static __device__ float g_a [NN * NN];
static __device__ float g_a2[NN * NN];
static __device__ __nv_bfloat16 g_Mhi[MP * KP];            // [v][w] row-major
static __device__ __nv_bfloat16 g_Mlo[MP * KP];
static __device__ __nv_bfloat16 g_Bhi[(size_t)NJ * KP];    // [j][w]
static __device__ __nv_bfloat16 g_Blo[(size_t)NJ * KP];

#define FMA_F32X2(d, a, b, c) \
    asm("fma.rn.f32x2 %0, %1, %2, %3;" : "=l"(d) : "l"(a), "l"(b), "l"(c))

__device__ __forceinline__ ull pack2(float x) {
    ull r; uint xi = __float_as_uint(x);
    asm("mov.b64 %0, {%1, %1};" : "=l"(r) : "r"(xi));
    return r;
}
// pack two f32 -> bf16x2: flo -> low half (first in memory)
#define CVT2BF(r, flo, fhi) \
    asm("cvt.rn.bf16x2.f32 %0, %1, %2;" : "=r"(r) : "f"(fhi), "f"(flo))

__device__ __forceinline__ uint smem_u32(const void* p) {
    uint a;
    asm("{ .reg .u64 t; cvta.to.shared.u64 t, %1; cvt.u32.u64 %0, t; }"
        : "=r"(a) : "l"(p));
    return a;
}

__device__ __forceinline__ void ldsm4(uint* r, uint addr) {
    asm volatile("ldmatrix.sync.aligned.m8n8.x4.shared.b16 {%0,%1,%2,%3}, [%4];"
        : "=r"(r[0]), "=r"(r[1]), "=r"(r[2]), "=r"(r[3]) : "r"(addr));
}
__device__ __forceinline__ void mma16816(float* c, const uint* a, const uint* b) {
    asm volatile("mma.sync.aligned.m16n8k16.row.col.f32.bf16.bf16.f32 "
        "{%0,%1,%2,%3}, {%4,%5,%6,%7}, {%8,%9}, {%0,%1,%2,%3};"
        : "+f"(c[0]), "+f"(c[1]), "+f"(c[2]), "+f"(c[3])
        : "r"(a[0]), "r"(a[1]), "r"(a[2]), "r"(a[3]), "r"(b[0]), "r"(b[1]));
}

// ---------------------------------------------------------------------------
// K1: row-normalize (adj + I)
// ---------------------------------------------------------------------------
__global__ void k_norm_adj(const float* __restrict__ adj) {
    int v = blockIdx.x, t = threadIdx.x;
    __shared__ float red[256];
    float s = 0.f;
    for (int w = t; w < NN; w += 256) s += adj[v * NN + w];
    red[t] = s; __syncthreads();
    for (int k = 128; k > 0; k >>= 1) { if (t < k) red[t] += red[t + k]; __syncthreads(); }
    float inv = 1.f / (red[0] + 1.f);
    for (int w = t; w < NN; w += 256)
        g_a[v * NN + w] = (adj[v * NN + w] + (w == v ? 1.f : 0.f)) * inv;
}

// K2: a2 = a @ a
__global__ void k_a2() {
    int v = blockIdx.x, t = threadIdx.x;
    __shared__ float av[NN];
    for (int w = t; w < NN; w += 224) av[w] = g_a[v * NN + w];
    __syncthreads();
    if (t < NN) {
        float acc = 0.f;
        #pragma unroll 4
        for (int w = 0; w < NN; ++w) acc = fmaf(av[w], g_a[w * NN + t], acc);
        g_a2[v * NN + t] = acc;
    }
}

// K3: M row v -> bf16 hi/lo, padded [256][208] (pad rows/cols = 0)
__global__ void k_m() {   // grid 256, block 224
    int v = blockIdx.x, t = threadIdx.x;
    __shared__ float av[NN], a2v[NN];
    bool vin = v < NN;
    if (vin)
        for (int w = t; w < NN; w += 224) { av[w] = g_a[v*NN+w]; a2v[w] = g_a2[v*NN+w]; }
    __syncthreads();
    if (t < KP) {
        float m = 0.f;
        if (vin && t < NN) {
            float a3 = 0.f;
            #pragma unroll 4
            for (int w = 0; w < NN; ++w) a3 = fmaf(a2v[w], g_a[w * NN + t], a3);
            m = 0.0475f * av[t] + 0.045125f * a2v[t] + 0.857375f * a3;
            if (t == v) m += 0.05f;
        }
        __nv_bfloat16 h = __float2bfloat16(m);
        g_Mhi[v * KP + t] = h;
        g_Mlo[v * KP + t] = __float2bfloat16(m - __bfloat162float(h));
    }
}

// ---------------------------------------------------------------------------
// K4: chanmix + split-bf16 emit: u[b,o,w,l] -> g_B{hi,lo}[(b*32+o)*12+l][w]
// grid (13, 256), block 192 = 32 o x 6 lpairs; w-tile 16 (last zero-padded)
// ---------------------------------------------------------------------------
__global__ void __launch_bounds__(192) k_chanmix(const float* __restrict__ x,
                                                 const float* __restrict__ W) {
    int b  = blockIdx.y;
    int w0 = blockIdx.x * 16;
    int nw = NN - w0; if (nw > 16) nw = 16;
    int t  = threadIdx.x;

    __shared__ __align__(16) float xs[CH * LT * 16];   // [c][l][wi]
    __shared__ ull Wcs[CH * CH];                       // [c][o] splat

    for (int i = t; i < CH * CH; i += 192) {
        int c = i >> 5, o = i & 31;
        Wcs[i] = pack2(W[o * CH + c]);
    }
    int nload = CH * nw * 3;
    for (int i = t; i < nload; i += 192) {
        int c  = i / (nw * 3);
        int r  = i - c * nw * 3;
        int wi = r / 3;
        int l4 = r - wi * 3;
        float4 v = *(const float4*)(x + ((size_t)(b * CH + c) * NN + (w0 + wi)) * LT + l4 * 4);
        xs[(c * LT + l4 * 4 + 0) * 16 + wi] = v.x;
        xs[(c * LT + l4 * 4 + 1) * 16 + wi] = v.y;
        xs[(c * LT + l4 * 4 + 2) * 16 + wi] = v.z;
        xs[(c * LT + l4 * 4 + 3) * 16 + wi] = v.w;
    }
    if (nw < 16) {
        for (int i = t; i < CH * LT * (16 - nw); i += 192) {
            int cl = i / (16 - nw), wi = nw + i % (16 - nw);
            xs[cl * 16 + wi] = 0.f;
        }
    }
    __syncthreads();

    int o  = t & 31;
    int lp = t >> 5;
    ull acc[2][8];
    #pragma unroll
    for (int li = 0; li < 2; ++li)
        #pragma unroll
        for (int k = 0; k < 8; ++k) acc[li][k] = 0ull;

    #pragma unroll 4
    for (int c = 0; c < CH; ++c) {
        ull wv = Wcs[c * CH + o];
        #pragma unroll
        for (int li = 0; li < 2; ++li) {
            const float4* xl = (const float4*)&xs[(c * LT + lp * 2 + li) * 16];
            #pragma unroll
            for (int q = 0; q < 4; ++q) {
                float4 f = xl[q];
                ull u0 = *(const ull*)&f.x;
                ull u1 = *(const ull*)&f.z;
                FMA_F32X2(acc[li][2*q],   wv, u0, acc[li][2*q]);
                FMA_F32X2(acc[li][2*q+1], wv, u1, acc[li][2*q+1]);
            }
        }
    }

    #pragma unroll
    for (int li = 0; li < 2; ++li) {
        int l = lp * 2 + li;
        size_t row = (size_t)(b * CH + o) * LT + l;
        uint hi[8], lo[8];
        #pragma unroll
        for (int k = 0; k < 8; ++k) {
            float fa = __uint_as_float((uint)(acc[li][k]));
            float fb = __uint_as_float((uint)(acc[li][k] >> 32));
            uint h; CVT2BF(h, fa, fb);
            float ha = __uint_as_float(h << 16);
            float hb = __uint_as_float(h & 0xFFFF0000u);
            uint l2; CVT2BF(l2, fa - ha, fb - hb);
            hi[k] = h; lo[k] = l2;
        }
        char* dh = (char*)g_Bhi + row * (KP * 2) + w0 * 2;
        char* dl = (char*)g_Blo + row * (KP * 2) + w0 * 2;
        *(uint4*)(dh)      = make_uint4(hi[0], hi[1], hi[2], hi[3]);
        *(uint4*)(dh + 16) = make_uint4(hi[4], hi[5], hi[6], hi[7]);
        *(uint4*)(dl)      = make_uint4(lo[0], lo[1], lo[2], lo[3]);
        *(uint4*)(dl + 16) = make_uint4(lo[4], lo[5], lo[6], lo[7]);
    }
}

// ---------------------------------------------------------------------------
// K5: HMMA GEMM  D[v,j] = sum_w M[v,w] U[j,w]  (3-pass bf16 hi/lo), +bias
// grid 1536 (j-tiles of 64), block 256 = 8 warps: (mw 0..3) x (nw 0..1)
// warp tile: m64 x n32.  B (full K) in smem; A streamed k16, double-buffered.
// ---------------------------------------------------------------------------
#define BPITCH 432                       // B smem row pitch bytes (216 bf16)
#define SM_BHI 0
#define SM_BLO (64 * BPITCH)             // 27648
#define SM_A   (2 * 64 * BPITCH)         // 55296
#define ABUF   16384                     // per chunk: hi 8192 + lo 8192
#define SM_TOT (SM_A + 2 * ABUF)         // 88064

__global__ void __launch_bounds__(256, 2) k_gemm(const float* __restrict__ bias,
                                                 float* __restrict__ out) {
    extern __shared__ __align__(16) char sm[];
    const uint smb = smem_u32(sm);
    int tid = threadIdx.x, lane = tid & 31, warp = tid >> 5;
    int mw = warp >> 1, nw = warp & 1;
    size_t j0 = (size_t)blockIdx.x * JT;

    // ---- load B (hi+lo) for all K ----
    const char* bh = (const char*)g_Bhi + j0 * (KP * 2);
    const char* bl = (const char*)g_Blo + j0 * (KP * 2);
    for (int i = tid; i < 64 * 26; i += 256) {
        int r = i / 26, q = i - r * 26;
        *(float4*)(sm + SM_BHI + r * BPITCH + q * 16) = *(const float4*)(bh + r * (KP*2) + q * 16);
        *(float4*)(sm + SM_BLO + r * BPITCH + q * 16) = *(const float4*)(bl + r * (KP*2) + q * 16);
    }
    // ---- load A chunk 0 ----
    #pragma unroll
    for (int it = 0; it < 4; ++it) {
        int i = tid + it * 256;
        int hl = i >> 9, rem = i & 511, m = rem >> 1, half = rem & 1;
        const char* src = (const char*)(hl ? g_Mlo : g_Mhi) + m * (KP*2) + half * 16;
        *(float4*)(sm + SM_A + hl * 8192 + m * 32 + ((half ^ ((m >> 2) & 1)) << 4))
            = *(const float4*)src;
    }
    __syncthreads();

    // per-thread ldmatrix address bases
    int aml = mw * 64 + (lane & 7) + ((lane >> 3) & 1) * 8;  // m_loc for mt=0
    int akh = lane >> 4;                                     // k half
    uint aoff = (uint)(aml * 32 + ((akh ^ ((aml >> 2) & 1)) << 4));
    int bnl = nw * 32 + (lane & 7) + ((lane >> 4) & 1) * 8;  // n_loc for npair=0
    int bkh = (lane >> 3) & 1;
    uint boff = (uint)(bnl * BPITCH + bkh * 16);

    float acc[16][4];
    #pragma unroll
    for (int i = 0; i < 16; ++i)
        #pragma unroll
        for (int k = 0; k < 4; ++k) acc[i][k] = 0.f;

    for (int c = 0; c < 13; ++c) {
        int buf = c & 1;
        // prefetch A chunk c+1 (global -> regs)
        float4 pf[4];
        if (c < 12) {
            #pragma unroll
            for (int it = 0; it < 4; ++it) {
                int i = tid + it * 256;
                int hl = i >> 9, rem = i & 511, m = rem >> 1, half = rem & 1;
                pf[it] = *(const float4*)((const char*)(hl ? g_Mlo : g_Mhi)
                                          + m * (KP*2) + (c + 1) * 32 + half * 16);
            }
        }

        uint abase = smb + SM_A + buf * ABUF + aoff;
        uint bbase = smb + boff + c * 32;
        uint Ahi[4][4], Alo[4][4], Bhi[2][4], Blo[2][4];
        #pragma unroll
        for (int mt = 0; mt < 4; ++mt) ldsm4(Ahi[mt], abase + mt * 512);
        #pragma unroll
        for (int np = 0; np < 2; ++np) ldsm4(Bhi[np], bbase + SM_BHI + np * (16 * BPITCH));
        #pragma unroll
        for (int mt = 0; mt < 4; ++mt)
            #pragma unroll
            for (int nt = 0; nt < 4; ++nt)
                mma16816(acc[mt * 4 + nt], Ahi[mt], &Bhi[nt >> 1][(nt & 1) * 2]);
        #pragma unroll
        for (int mt = 0; mt < 4; ++mt) ldsm4(Alo[mt], abase + 8192 + mt * 512);
        #pragma unroll
        for (int mt = 0; mt < 4; ++mt)
            #pragma unroll
            for (int nt = 0; nt < 4; ++nt)
                mma16816(acc[mt * 4 + nt], Alo[mt], &Bhi[nt >> 1][(nt & 1) * 2]);
        #pragma unroll
        for (int np = 0; np < 2; ++np) ldsm4(Blo[np], bbase + SM_BLO + np * (16 * BPITCH));
        #pragma unroll
        for (int mt = 0; mt < 4; ++mt)
            #pragma unroll
            for (int nt = 0; nt < 4; ++nt)
                mma16816(acc[mt * 4 + nt], Ahi[mt], &Blo[nt >> 1][(nt & 1) * 2]);

        if (c < 12) {
            #pragma unroll
            for (int it = 0; it < 4; ++it) {
                int i = tid + it * 256;
                int hl = i >> 9, rem = i & 511, m = rem >> 1, half = rem & 1;
                *(float4*)(sm + SM_A + (buf ^ 1) * ABUF + hl * 8192 + m * 32
                           + ((half ^ ((m >> 2) & 1)) << 4)) = pf[it];
            }
        }
        __syncthreads();
    }

    // ---- epilogue: per-thread j pointers, fused bias, direct stores ----
    float bv[4][2];
    float* pj[4][2];
    int jcol = (lane & 3) * 2;
    #pragma unroll
    for (int nt = 0; nt < 4; ++nt)
        #pragma unroll
        for (int e = 0; e < 2; ++e) {
            int jj = (int)j0 + nw * 32 + nt * 8 + jcol + e;
            int b = jj / (CH * LT);
            int o = (jj / LT) & (CH - 1);
            int l = jj - (jj / LT) * LT;
            pj[nt][e] = out + ((size_t)(b * CH + o) * NN) * LT + l;
            bv[nt][e] = __ldg(bias + o);
        }
    int vr = lane >> 2;
    #pragma unroll
    for (int mt = 0; mt < 4; ++mt)
        #pragma unroll
        for (int rh = 0; rh < 2; ++rh) {
            int v = mw * 64 + mt * 16 + rh * 8 + vr;
            if (v < NN) {
                #pragma unroll
                for (int nt = 0; nt < 4; ++nt)
                    #pragma unroll
                    for (int e = 0; e < 2; ++e)
                        pj[nt][e][(size_t)v * LT] = acc[mt * 4 + nt][rh * 2 + e] + bv[nt][e];
            }
        }
}

// ---------------------------------------------------------------------------
extern "C" void kernel_launch(void* const* d_in, const int* in_sizes, int n_in,
                              void* d_out, int out_size) {
    const float* x   = (const float*)d_in[0];
    const float* adj = (const float*)d_in[1];
    const float* W   = (const float*)d_in[2];
    const float* bia = (const float*)d_in[3];
    float* out = (float*)d_out;

    static int cfg = 0;
    if (!cfg) {
        cudaFuncSetAttribute(k_gemm, cudaFuncAttributeMaxDynamicSharedMemorySize, SM_TOT);
        cfg = 1;
    }

    k_norm_adj<<<NN, 256>>>(adj);
    k_a2      <<<NN, 224>>>();
    k_m       <<<MP, 224>>>();
    k_chanmix <<<dim3(13, BATCH), 192>>>(x, W);
    k_gemm    <<<NJ / JT, 256, SM_TOT>>>(bia, out);
}

// round 7
// speedup vs baseline: 2.1285x; 1.1227x over previous
#include <cuda_runtime.h>
#include <cuda_fp16.h>
#include <cstdint>

// ---------------------------------------------------------------------------
// out[b,o,v,l] = sum_c W[o,c] * (M x)[b,c,v,l] + bias[o]
// M = 0.05*I + 0.0475*A + 0.045125*A^2 + 0.857375*A^3,  A = row-norm(adj+I)
// Path: fold diffusion into M; chanmix -> fp16 U[j][w] (j=(b,o,l));
// mma.sync fp16 2-pass GEMM D[v,j] = (Mhi + Mlo)[v,:]·U[j,:], U single fp16.
// (tcgen05 unavailable: harness builds via compute_103 virtual arch.)
// ---------------------------------------------------------------------------

#define NN    207
#define KP    208                 // padded K (w), 13 x k16
#define MP    256                 // padded M (v)
#define BATCH 256
#define CH    32
#define LT    12
#define NJ    (BATCH * CH * LT)   // 98304
#define JT    96                  // j per CTA = 8 o x 12 l (aligned)

typedef unsigned long long ull;
typedef unsigned int uint;

static __device__ float g_a [NN * NN];
static __device__ float g_a2[NN * NN];
static __device__ __half g_Mhi[MP * KP];            // [v][w] row-major
static __device__ __half g_Mlo[MP * KP];
static __device__ __half g_B  [(size_t)NJ * KP];    // U fp16 [j][w], pitch 416B

#define FMA_F32X2(d, a, b, c) \
    asm("fma.rn.f32x2 %0, %1, %2, %3;" : "=l"(d) : "l"(a), "l"(b), "l"(c))

__device__ __forceinline__ ull pack2(float x) {
    ull r; uint xi = __float_as_uint(x);
    asm("mov.b64 %0, {%1, %1};" : "=l"(r) : "r"(xi));
    return r;
}
// pack two f32 -> f16x2: flo -> low half (first in memory)
#define CVT2HF(r, flo, fhi) \
    asm("cvt.rn.f16x2.f32 %0, %1, %2;" : "=r"(r) : "f"(fhi), "f"(flo))

__device__ __forceinline__ uint smem_u32(const void* p) {
    uint a;
    asm("{ .reg .u64 t; cvta.to.shared.u64 t, %1; cvt.u32.u64 %0, t; }"
        : "=r"(a) : "l"(p));
    return a;
}

__device__ __forceinline__ void ldsm4(uint* r, uint addr) {
    asm volatile("ldmatrix.sync.aligned.m8n8.x4.shared.b16 {%0,%1,%2,%3}, [%4];"
        : "=r"(r[0]), "=r"(r[1]), "=r"(r[2]), "=r"(r[3]) : "r"(addr));
}
__device__ __forceinline__ void mma16816(float* c, const uint* a, const uint* b) {
    asm volatile("mma.sync.aligned.m16n8k16.row.col.f32.f16.f16.f32 "
        "{%0,%1,%2,%3}, {%4,%5,%6,%7}, {%8,%9}, {%0,%1,%2,%3};"
        : "+f"(c[0]), "+f"(c[1]), "+f"(c[2]), "+f"(c[3])
        : "r"(a[0]), "r"(a[1]), "r"(a[2]), "r"(a[3]), "r"(b[0]), "r"(b[1]));
}

// ---------------------------------------------------------------------------
// K1: row-normalize (adj + I)
// ---------------------------------------------------------------------------
__global__ void k_norm_adj(const float* __restrict__ adj) {
    int v = blockIdx.x, t = threadIdx.x;
    __shared__ float red[256];
    float s = 0.f;
    for (int w = t; w < NN; w += 256) s += adj[v * NN + w];
    red[t] = s; __syncthreads();
    for (int k = 128; k > 0; k >>= 1) { if (t < k) red[t] += red[t + k]; __syncthreads(); }
    float inv = 1.f / (red[0] + 1.f);
    for (int w = t; w < NN; w += 256)
        g_a[v * NN + w] = (adj[v * NN + w] + (w == v ? 1.f : 0.f)) * inv;
}

// K2: a2 = a @ a
__global__ void k_a2() {
    int v = blockIdx.x, t = threadIdx.x;
    __shared__ float av[NN];
    for (int w = t; w < NN; w += 224) av[w] = g_a[v * NN + w];
    __syncthreads();
    if (t < NN) {
        float acc = 0.f;
        #pragma unroll 4
        for (int w = 0; w < NN; ++w) acc = fmaf(av[w], g_a[w * NN + t], acc);
        g_a2[v * NN + t] = acc;
    }
}

// K3: M row v -> fp16 hi + residual lo, padded [256][208]
__global__ void k_m() {   // grid 256, block 224
    int v = blockIdx.x, t = threadIdx.x;
    __shared__ float av[NN], a2v[NN];
    bool vin = v < NN;
    if (vin)
        for (int w = t; w < NN; w += 224) { av[w] = g_a[v*NN+w]; a2v[w] = g_a2[v*NN+w]; }
    __syncthreads();
    if (t < KP) {
        float m = 0.f;
        if (vin && t < NN) {
            float a3 = 0.f;
            #pragma unroll 4
            for (int w = 0; w < NN; ++w) a3 = fmaf(a2v[w], g_a[w * NN + t], a3);
            m = 0.0475f * av[t] + 0.045125f * a2v[t] + 0.857375f * a3;
            if (t == v) m += 0.05f;
        }
        __half h = __float2half_rn(m);
        g_Mhi[v * KP + t] = h;
        g_Mlo[v * KP + t] = __float2half_rn(m - __half2float(h));
    }
}

// ---------------------------------------------------------------------------
// K4: chanmix + fp16 emit: u[b,o,w,l] -> g_B[(b*32+o)*12+l][w]
// grid (13, 256), block 192 = 32 o x 6 lpairs; w-tile 16 (last zero-padded)
// ---------------------------------------------------------------------------
__global__ void __launch_bounds__(192) k_chanmix(const float* __restrict__ x,
                                                 const float* __restrict__ W) {
    int b  = blockIdx.y;
    int w0 = blockIdx.x * 16;
    int nw = NN - w0; if (nw > 16) nw = 16;
    int t  = threadIdx.x;

    __shared__ __align__(16) float xs[CH * LT * 16];   // [c][l][wi]
    __shared__ ull Wcs[CH * CH];                       // [c][o] splat

    for (int i = t; i < CH * CH; i += 192) {
        int c = i >> 5, o = i & 31;
        Wcs[i] = pack2(W[o * CH + c]);
    }
    int nload = CH * nw * 3;
    for (int i = t; i < nload; i += 192) {
        int c  = i / (nw * 3);
        int r  = i - c * nw * 3;
        int wi = r / 3;
        int l4 = r - wi * 3;
        float4 v = *(const float4*)(x + ((size_t)(b * CH + c) * NN + (w0 + wi)) * LT + l4 * 4);
        xs[(c * LT + l4 * 4 + 0) * 16 + wi] = v.x;
        xs[(c * LT + l4 * 4 + 1) * 16 + wi] = v.y;
        xs[(c * LT + l4 * 4 + 2) * 16 + wi] = v.z;
        xs[(c * LT + l4 * 4 + 3) * 16 + wi] = v.w;
    }
    if (nw < 16) {
        for (int i = t; i < CH * LT * (16 - nw); i += 192) {
            int cl = i / (16 - nw), wi = nw + i % (16 - nw);
            xs[cl * 16 + wi] = 0.f;
        }
    }
    __syncthreads();

    int o  = t & 31;
    int lp = t >> 5;
    ull acc[2][8];
    #pragma unroll
    for (int li = 0; li < 2; ++li)
        #pragma unroll
        for (int k = 0; k < 8; ++k) acc[li][k] = 0ull;

    #pragma unroll 4
    for (int c = 0; c < CH; ++c) {
        ull wv = Wcs[c * CH + o];
        #pragma unroll
        for (int li = 0; li < 2; ++li) {
            const float4* xl = (const float4*)&xs[(c * LT + lp * 2 + li) * 16];
            #pragma unroll
            for (int q = 0; q < 4; ++q) {
                float4 f = xl[q];
                ull u0 = *(const ull*)&f.x;
                ull u1 = *(const ull*)&f.z;
                FMA_F32X2(acc[li][2*q],   wv, u0, acc[li][2*q]);
                FMA_F32X2(acc[li][2*q+1], wv, u1, acc[li][2*q+1]);
            }
        }
    }

    #pragma unroll
    for (int li = 0; li < 2; ++li) {
        int l = lp * 2 + li;
        size_t row = (size_t)(b * CH + o) * LT + l;
        uint hf[8];
        #pragma unroll
        for (int k = 0; k < 8; ++k) {
            float fa = __uint_as_float((uint)(acc[li][k]));
            float fb = __uint_as_float((uint)(acc[li][k] >> 32));
            CVT2HF(hf[k], fa, fb);
        }
        char* dh = (char*)g_B + row * (KP * 2) + w0 * 2;
        *(uint4*)(dh)      = make_uint4(hf[0], hf[1], hf[2], hf[3]);
        *(uint4*)(dh + 16) = make_uint4(hf[4], hf[5], hf[6], hf[7]);
    }
}

// ---------------------------------------------------------------------------
// K5: HMMA GEMM  D[v,j] = sum_w (Mhi+Mlo)[v,w] U[j,w], fp16 2-pass, +bias
// grid (2 vtiles of 128, 1024 jtiles of 96), block 256 = 8 warps (4 mw x 2 nw)
// warp tile m32 x n48.  B (full K) in smem; A streamed k16, double-buffered.
// Epilogue: stage D in smem, write out fully coalesced along l.
// ---------------------------------------------------------------------------
#define BPITCH 432
#define SM_B   0
#define SM_A   41472                 // 96 * 432
#define SM_TOT (41472 + 16384)       // + 2 bufs x (hi 4K + lo 4K) = 57856

__global__ void __launch_bounds__(256, 2) k_gemm(const float* __restrict__ bias,
                                                 float* __restrict__ out) {
    extern __shared__ __align__(16) char sm[];
    const uint smb = smem_u32(sm);
    int tid = threadIdx.x, lane = tid & 31, warp = tid >> 5;
    int mw = warp >> 1, nw = warp & 1;
    int v0 = blockIdx.x * 128;
    size_t j0 = (size_t)blockIdx.y * JT;

    // ---- load B (fp16, full K) ----
    const char* bsrc = (const char*)g_B + j0 * (KP * 2);
    for (int i = tid; i < 96 * 26; i += 256) {
        int r = i / 26, q = i - r * 26;
        *(float4*)(sm + SM_B + r * BPITCH + q * 16) = *(const float4*)(bsrc + r * (KP*2) + q * 16);
    }
    // ---- load A chunk 0 (hi + lo, 128 rows x 16 halves) ----
    #pragma unroll
    for (int it = 0; it < 2; ++it) {
        int i = tid + it * 256;
        int hl = i >> 8, rem = i & 255, m = rem >> 1, half = rem & 1;
        const char* s = (const char*)(hl ? g_Mlo : g_Mhi) + (size_t)(v0 + m) * (KP*2) + half * 16;
        *(float4*)(sm + SM_A + hl * 4096 + m * 32 + ((half ^ ((m >> 2) & 1)) << 4))
            = *(const float4*)s;
    }
    __syncthreads();

    int aml = mw * 32 + (lane & 7) + ((lane >> 3) & 1) * 8;
    int akh = lane >> 4;
    uint aoff = (uint)(aml * 32 + ((akh ^ ((aml >> 2) & 1)) << 4));
    int bnl = nw * 48 + (lane & 7) + ((lane >> 4) & 1) * 8;
    int bkh = (lane >> 3) & 1;
    uint boff = (uint)(bnl * BPITCH + bkh * 16);

    float acc[12][4];
    #pragma unroll
    for (int i = 0; i < 12; ++i)
        #pragma unroll
        for (int k = 0; k < 4; ++k) acc[i][k] = 0.f;

    for (int c = 0; c < 13; ++c) {
        int buf = c & 1;
        float4 pf[2];
        if (c < 12) {
            #pragma unroll
            for (int it = 0; it < 2; ++it) {
                int i = tid + it * 256;
                int hl = i >> 8, rem = i & 255, m = rem >> 1, half = rem & 1;
                pf[it] = *(const float4*)((const char*)(hl ? g_Mlo : g_Mhi)
                                          + (size_t)(v0 + m) * (KP*2) + (c + 1) * 32 + half * 16);
            }
        }

        uint ab = smb + SM_A + buf * 8192 + aoff;
        uint bb = smb + SM_B + boff + c * 32;
        uint B[3][4], Ah[2][4], Al[2][4];
        #pragma unroll
        for (int np = 0; np < 3; ++np) ldsm4(B[np], bb + np * (16 * BPITCH));
        #pragma unroll
        for (int mt = 0; mt < 2; ++mt) ldsm4(Ah[mt], ab + mt * 512);
        #pragma unroll
        for (int mt = 0; mt < 2; ++mt)
            #pragma unroll
            for (int nt = 0; nt < 6; ++nt)
                mma16816(acc[mt * 6 + nt], Ah[mt], &B[nt >> 1][(nt & 1) * 2]);
        #pragma unroll
        for (int mt = 0; mt < 2; ++mt) ldsm4(Al[mt], ab + 4096 + mt * 512);
        #pragma unroll
        for (int mt = 0; mt < 2; ++mt)
            #pragma unroll
            for (int nt = 0; nt < 6; ++nt)
                mma16816(acc[mt * 6 + nt], Al[mt], &B[nt >> 1][(nt & 1) * 2]);

        if (c < 12) {
            #pragma unroll
            for (int it = 0; it < 2; ++it) {
                int i = tid + it * 256;
                int hl = i >> 8, rem = i & 255, m = rem >> 1, half = rem & 1;
                *(float4*)(sm + SM_A + (buf ^ 1) * 8192 + hl * 4096 + m * 32
                           + ((half ^ ((m >> 2) & 1)) << 4)) = pf[it];
            }
        }
        __syncthreads();
    }

    // ---- epilogue: stage D[128][96] (pitch 100), then coalesced out ----
    float* stage = (float*)sm;
    int jc = (lane & 3) * 2, vr = lane >> 2;
    #pragma unroll
    for (int mt = 0; mt < 2; ++mt)
        #pragma unroll
        for (int nt = 0; nt < 6; ++nt)
            #pragma unroll
            for (int rh = 0; rh < 2; ++rh) {
                int v = mw * 32 + mt * 16 + rh * 8 + vr;
                int jl = nw * 48 + nt * 8 + jc;
                stage[v * 100 + jl]     = acc[mt * 6 + nt][rh * 2];
                stage[v * 100 + jl + 1] = acc[mt * 6 + nt][rh * 2 + 1];
            }
    __syncthreads();

    int b  = (int)(j0 / 384);
    int ob = ((int)j0 % 384) / 12;
    int nv = NN - v0; if (nv > 128) nv = 128;
    for (int i = tid; i < 3072; i += 256) {
        int o = i / 384, rem = i - o * 384, v = rem / 3, q = rem - v * 3;
        if (v < nv) {
            float4 d = *(float4*)&stage[v * 100 + o * 12 + q * 4];
            float bv = __ldg(bias + ob + o);
            d.x += bv; d.y += bv; d.z += bv; d.w += bv;
            *(float4*)(out + ((size_t)(b * CH + ob + o) * NN + v0 + v) * LT + q * 4) = d;
        }
    }
}

// ---------------------------------------------------------------------------
extern "C" void kernel_launch(void* const* d_in, const int* in_sizes, int n_in,
                              void* d_out, int out_size) {
    const float* x   = (const float*)d_in[0];
    const float* adj = (const float*)d_in[1];
    const float* W   = (const float*)d_in[2];
    const float* bia = (const float*)d_in[3];
    float* out = (float*)d_out;

    static int cfg = 0;
    if (!cfg) {
        cudaFuncSetAttribute(k_gemm, cudaFuncAttributeMaxDynamicSharedMemorySize, SM_TOT);
        cfg = 1;
    }

    k_norm_adj<<<NN, 256>>>(adj);
    k_a2      <<<NN, 224>>>();
    k_m       <<<MP, 224>>>();
    k_chanmix <<<dim3(13, BATCH), 192>>>(x, W);
    k_gemm    <<<dim3(2, NJ / JT), 256, SM_TOT>>>(bia, out);
}